// round 1
// baseline (speedup 1.0000x reference)
#include <cuda_runtime.h>
#include <math.h>

#define BB   128
#define TT   200
#define VV   50257
#define HH   256
#define EE   128
#define NOOV 50
#define KIN  640            // 2H + E
#define G3   768            // 3H
#define VO   (VV + NOOV)    // 50307
#define BT   (BB * TT)      // 25600

// ---------------- scratch (device globals; no allocation allowed) ----------
__device__ float g_gru_in[BB * KIN];
__device__ float g_gi[BB * G3];
__device__ float g_gh[BB * G3];
__device__ float g_dh[BB * HH];
__device__ float g_score[BB * VV];   // score_g (25.7 MB)
__device__ float g_scraw[BT];        // score_c accum -> masked score_c
__device__ float g_probc[BT];

// ---------------- K0: assemble gru_in = [selective_read | emb[dec]] --------
__global__ void k_gruin(const int* __restrict__ dec,
                        const float* __restrict__ sr,
                        const float* __restrict__ emb) {
    int b = blockIdx.x;
    int i = threadIdx.x;                       // 640 threads
    float v;
    if (i < 2 * HH) v = sr[b * 2 * HH + i];
    else            v = emb[(size_t)dec[b] * EE + (i - 2 * HH)];
    g_gru_in[b * KIN + i] = v;
}

// ---------------- generic GEMM: C[128,N] = A[128,K] @ W[N,K]^T + bias ------
// block tile 128(M) x 64(N), 256 threads, thread tile 8x4. K % 16 == 0.
__global__ void k_gemm128(const float* __restrict__ A,
                          const float* __restrict__ W,
                          const float* __restrict__ bias,
                          float* __restrict__ C, int N, int K) {
    __shared__ float sA[128][17];
    __shared__ float sB[64][17];
    int tid = threadIdx.x;
    int n0  = blockIdx.x * 64;
    int rb  = (tid >> 4) * 8;    // 16 m-groups * 8 rows
    int cb  = (tid & 15) * 4;    // 16 n-groups * 4 cols
    float acc[8][4];
#pragma unroll
    for (int i = 0; i < 8; i++)
#pragma unroll
        for (int j = 0; j < 4; j++) acc[i][j] = 0.f;

    for (int k0 = 0; k0 < K; k0 += 16) {
        // A tile: 128x16 = 512 float4, 2 per thread
#pragma unroll
        for (int l = 0; l < 2; l++) {
            int idx4 = tid + l * 256;
            int row  = idx4 >> 2;
            int kp   = (idx4 & 3) * 4;
            float4 v = *(const float4*)(A + (size_t)row * K + k0 + kp);
            sA[row][kp + 0] = v.x; sA[row][kp + 1] = v.y;
            sA[row][kp + 2] = v.z; sA[row][kp + 3] = v.w;
        }
        // W tile: 64x16 = 256 float4, 1 per thread
        {
            int col = tid >> 2;
            int kp  = (tid & 3) * 4;
            float4 v = make_float4(0.f, 0.f, 0.f, 0.f);
            if (n0 + col < N)
                v = *(const float4*)(W + (size_t)(n0 + col) * K + k0 + kp);
            sB[col][kp + 0] = v.x; sB[col][kp + 1] = v.y;
            sB[col][kp + 2] = v.z; sB[col][kp + 3] = v.w;
        }
        __syncthreads();
#pragma unroll
        for (int kk = 0; kk < 16; kk++) {
            float a[8], bv[4];
#pragma unroll
            for (int i = 0; i < 8; i++) a[i] = sA[rb + i][kk];
#pragma unroll
            for (int j = 0; j < 4; j++) bv[j] = sB[cb + j][kk];
#pragma unroll
            for (int i = 0; i < 8; i++)
#pragma unroll
                for (int j = 0; j < 4; j++) acc[i][j] = fmaf(a[i], bv[j], acc[i][j]);
        }
        __syncthreads();
    }
#pragma unroll
    for (int i = 0; i < 8; i++) {
        int r = rb + i;
#pragma unroll
        for (int j = 0; j < 4; j++) {
            int c = n0 + cb + j;
            if (c < N) C[(size_t)r * N + c] = acc[i][j] + bias[c];
        }
    }
}

// ---------------- K2: GRU elementwise gate fusion --------------------------
__global__ void k_gru(const float* __restrict__ hprev, float* __restrict__ out_dh) {
    int b = blockIdx.x, j = threadIdx.x;   // 256 threads
    const float* gi = g_gi + b * G3;
    const float* gh = g_gh + b * G3;
    float r  = 1.f / (1.f + expf(-(gi[j] + gh[j])));
    float z  = 1.f / (1.f + expf(-(gi[HH + j] + gh[HH + j])));
    float n  = tanhf(gi[2 * HH + j] + r * gh[2 * HH + j]);
    float h  = hprev[b * HH + j];
    float dh = (1.f - z) * n + z * h;
    g_dh[b * HH + j]   = dh;
    out_dh[b * HH + j] = dh;
}

// ---------------- K4: zero score_c accumulator ------------------------------
__global__ void k_zero_scraw() {
    g_scraw[blockIdx.x * 256 + threadIdx.x] = 0.f;   // grid 100 * 256 == BT
}

// ---------------- K5: fused enc_proj GEMM + tanh + dot(dh) -----------------
// rows = B*T (row r -> b=r/T), cols = H, K = 2H. Tile 64x64, epilogue reduces
// tanh(acc+bias)*dh over cols into g_scraw[row] atomically.
__global__ void k_enc(const float* __restrict__ EO,
                      const float* __restrict__ Wc,
                      const float* __restrict__ cbias) {
    __shared__ float sA[64][17];
    __shared__ float sB[64][17];
    __shared__ float red[64];
    int tid = threadIdx.x;
    int r0  = blockIdx.x * 64;   // 400 blocks
    int n0  = blockIdx.y * 64;   // 4 blocks
    int rb  = (tid >> 4) * 4;
    int cbn = (tid & 15) * 4;
    float acc[4][4];
#pragma unroll
    for (int i = 0; i < 4; i++)
#pragma unroll
        for (int j = 0; j < 4; j++) acc[i][j] = 0.f;

    for (int k0 = 0; k0 < 2 * HH; k0 += 16) {
        int row = tid >> 2;
        int kp  = (tid & 3) * 4;
        float4 va = *(const float4*)(EO + (size_t)(r0 + row) * (2 * HH) + k0 + kp);
        sA[row][kp + 0] = va.x; sA[row][kp + 1] = va.y;
        sA[row][kp + 2] = va.z; sA[row][kp + 3] = va.w;
        float4 vb = *(const float4*)(Wc + (size_t)(n0 + row) * (2 * HH) + k0 + kp);
        sB[row][kp + 0] = vb.x; sB[row][kp + 1] = vb.y;
        sB[row][kp + 2] = vb.z; sB[row][kp + 3] = vb.w;
        __syncthreads();
#pragma unroll
        for (int kk = 0; kk < 16; kk++) {
            float a[4], bv[4];
#pragma unroll
            for (int i = 0; i < 4; i++) a[i] = sA[rb + i][kk];
#pragma unroll
            for (int j = 0; j < 4; j++) bv[j] = sB[cbn + j][kk];
#pragma unroll
            for (int i = 0; i < 4; i++)
#pragma unroll
                for (int j = 0; j < 4; j++) acc[i][j] = fmaf(a[i], bv[j], acc[i][j]);
        }
        __syncthreads();
    }
    if (tid < 64) red[tid] = 0.f;
    __syncthreads();
#pragma unroll
    for (int i = 0; i < 4; i++) {
        int gr = r0 + rb + i;
        int b  = gr / TT;
        float s = 0.f;
#pragma unroll
        for (int j = 0; j < 4; j++) {
            int c  = n0 + cbn + j;
            float v = tanhf(acc[i][j] + cbias[c]);
            s += v * g_dh[b * HH + c];
        }
        atomicAdd(&red[rb + i], s);
    }
    __syncthreads();
    if (tid < 64) atomicAdd(&g_scraw[r0 + tid], red[tid]);
}

// ---------------- K6: score_c = tanh(raw) + mask ----------------------------
__global__ void k_scmask(const int* __restrict__ idxs) {
    int i = blockIdx.x * 256 + threadIdx.x;   // grid 100
    float v = tanhf(g_scraw[i]);
    if (idxs[i] == 0) v -= 10000.f;
    g_scraw[i] = v;
}

// ---------------- K7: per-row softmax over [score_g | score_c] + output ----
__global__ void k_softmax(const int* __restrict__ idxs, float* __restrict__ out) {
    int b = blockIdx.x, tid = threadIdx.x;    // 256 threads
    __shared__ float sred[256];
    const float* sg = g_score + (size_t)b * VV;
    const float* sc = g_scraw + b * TT;
    // pass 1: max
    float m = -1e30f;
    for (int v = tid; v < VV; v += 256) m = fmaxf(m, sg[v]);
    for (int t = tid; t < TT; t += 256) m = fmaxf(m, sc[t]);
    sred[tid] = m; __syncthreads();
    for (int s = 128; s > 0; s >>= 1) {
        if (tid < s) sred[tid] = fmaxf(sred[tid], sred[tid + s]);
        __syncthreads();
    }
    m = sred[0]; __syncthreads();
    // pass 2: sum exp
    float sum = 0.f;
    for (int v = tid; v < VV; v += 256) sum += expf(sg[v] - m);
    for (int t = tid; t < TT; t += 256) sum += expf(sc[t] - m);
    sred[tid] = sum; __syncthreads();
    for (int s = 128; s > 0; s >>= 1) {
        if (tid < s) sred[tid] += sred[tid + s];
        __syncthreads();
    }
    float inv = 1.f / sred[0]; __syncthreads();
    // pass 3: write prob_g, OOV pad, prob_c
    float* orow = out + (size_t)b * VO;
    for (int v = tid; v < VV; v += 256) orow[v] = expf(sg[v] - m) * inv;
    for (int j = tid; j < NOOV; j += 256) orow[VV + j] = 1e-4f;
    for (int t = tid; t < TT; t += 256) g_probc[b * TT + t] = expf(sc[t] - m) * inv;
    __syncthreads();
    // scatter prob_c into this block's own output row (no cross-block races)
    for (int t = tid; t < TT; t += 256)
        atomicAdd(&orow[idxs[b * TT + t]], g_probc[b * TT + t]);
}

// ---------------- K8: selective_read (sparse match) -------------------------
__global__ void k_selread(const int* __restrict__ idxs, const int* __restrict__ dec,
                          const float* __restrict__ EO, float* __restrict__ out_sr) {
    int b = blockIdx.x, tid = threadIdx.x;    // 256 threads
    __shared__ int mt[TT];
    __shared__ int cnt;
    if (tid == 0) cnt = 0;
    __syncthreads();
    int d = dec[b];
    for (int t = tid; t < TT; t += 256)
        if (idxs[b * TT + t] == d) { int p = atomicAdd(&cnt, 1); mt[p] = t; }
    __syncthreads();
    int n = cnt;
    float scale = (n > 1) ? 1.f / (float)n : 1.f;
    for (int e = tid; e < 2 * HH; e += 256) {
        float acc = 0.f;
        for (int k = 0; k < n; k++) {
            int t = mt[k];
            acc += g_probc[b * TT + t] * scale *
                   EO[((size_t)b * TT + t) * (2 * HH) + e];
        }
        out_sr[b * 2 * HH + e] = acc;
    }
}

// ---------------- launch ----------------------------------------------------
extern "C" void kernel_launch(void* const* d_in, const int* in_sizes, int n_in,
                              void* d_out, int out_size) {
    const int*   dec  = (const int*)d_in[0];
    const float* EO   = (const float*)d_in[1];
    const int*   idxs = (const int*)d_in[2];
    const float* prev = (const float*)d_in[3];
    const float* sr   = (const float*)d_in[4];
    int off = (n_in >= 17 && in_sizes[5] == 1) ? 1 : 0;   // 'step' scalar present?
    const float* emb  = (const float*)d_in[5 + off];
    const float* W_ih = (const float*)d_in[6 + off];
    const float* W_hh = (const float*)d_in[7 + off];
    const float* b_ih = (const float*)d_in[8 + off];
    const float* b_hh = (const float*)d_in[9 + off];
    // Wi_w/Wi_b (10,11) unused: step == 1 always
    const float* Wg_w = (const float*)d_in[12 + off];
    const float* Wg_b = (const float*)d_in[13 + off];
    const float* Wc_w = (const float*)d_in[14 + off];
    const float* Wc_b = (const float*)d_in[15 + off];

    float* out      = (float*)d_out;
    float* out_dh   = out + (size_t)BB * VO;
    float* out_sr   = out_dh + (size_t)BB * HH;

    float *gi_p, *gh_p, *gin_p, *dh_p, *sg_p;
    cudaGetSymbolAddress((void**)&gin_p, g_gru_in);
    cudaGetSymbolAddress((void**)&gi_p,  g_gi);
    cudaGetSymbolAddress((void**)&gh_p,  g_gh);
    cudaGetSymbolAddress((void**)&dh_p,  g_dh);
    cudaGetSymbolAddress((void**)&sg_p,  g_score);

    k_gruin<<<BB, KIN>>>(dec, sr, emb);
    k_gemm128<<<G3 / 64, 256>>>(gin_p, W_ih, b_ih, gi_p, G3, KIN);
    k_gemm128<<<G3 / 64, 256>>>(prev,  W_hh, b_hh, gh_p, G3, HH);
    k_gru<<<BB, HH>>>(prev, out_dh);
    k_gemm128<<<(VV + 63) / 64, 256>>>(dh_p, Wg_w, Wg_b, sg_p, VV, HH);
    k_zero_scraw<<<BT / 256, 256>>>();
    k_enc<<<dim3(BT / 64, HH / 64), 256>>>(EO, Wc_w, Wc_b);
    k_scmask<<<BT / 256, 256>>>(idxs);
    k_softmax<<<BB, 256>>>(idxs, out);
    k_selread<<<BB, 256>>>(idxs, dec, EO, out_sr);
}

// round 2
// speedup vs baseline: 2.4203x; 2.4203x over previous
#include <cuda_runtime.h>
#include <math.h>
#include <stdint.h>

#define BB   128
#define TT   200
#define VV   50257
#define HH   256
#define EE   128
#define NOOV 50
#define KIN  640            // 2H + E
#define G3   768            // 3H
#define VO   (VV + NOOV)    // 50307
#define BT   (BB * TT)      // 25600
#define SPAD 36             // smem k-stride (conflict-free for mma frag loads)

// ---------------- scratch -----------------------------------------------
__device__ float g_gru_in[BB * KIN];
__device__ float g_gi[BB * G3];
__device__ float g_gh[BB * G3];
__device__ float g_dh[BB * HH];
__device__ float g_score[BB * VV];
__device__ float g_scraw[BT];       // masked score_c
__device__ float g_probc[BT];

// ---------------- helpers -------------------------------------------------
__device__ __forceinline__ uint32_t f2tf(float x) {
    uint32_t u; asm("cvt.rna.tf32.f32 %0, %1;" : "=r"(u) : "f"(x)); return u;
}
__device__ __forceinline__ void mma8(float* c, const uint32_t* a, const uint32_t* b) {
    asm volatile(
        "mma.sync.aligned.m16n8k8.row.col.f32.tf32.tf32.f32 "
        "{%0,%1,%2,%3}, {%4,%5,%6,%7}, {%8,%9}, {%0,%1,%2,%3};\n"
        : "+f"(c[0]), "+f"(c[1]), "+f"(c[2]), "+f"(c[3])
        : "r"(a[0]), "r"(a[1]), "r"(a[2]), "r"(a[3]), "r"(b[0]), "r"(b[1]));
}

// ---------------- K0: gru_in = [selective_read | emb[dec]] -----------------
__global__ void k_gruin(const int* __restrict__ dec,
                        const float* __restrict__ sr,
                        const float* __restrict__ emb) {
    int b = blockIdx.x, i = threadIdx.x;       // 640 threads
    float v;
    if (i < 2 * HH) v = sr[b * 2 * HH + i];
    else            v = emb[(size_t)dec[b] * EE + (i - 2 * HH)];
    g_gru_in[b * KIN + i] = v;
}

// ---------------- SIMT GEMM body for the small GRU gate GEMMs --------------
__device__ void gemm128_body(const float* __restrict__ A,
                             const float* __restrict__ W,
                             const float* __restrict__ bias,
                             float* __restrict__ C, int N, int K) {
    __shared__ float sA[128][17];
    __shared__ float sB[64][17];
    int tid = threadIdx.x;
    int n0  = blockIdx.x * 64;
    int rb  = (tid >> 4) * 8;
    int cb  = (tid & 15) * 4;
    float acc[8][4];
#pragma unroll
    for (int i = 0; i < 8; i++)
#pragma unroll
        for (int j = 0; j < 4; j++) acc[i][j] = 0.f;
    for (int k0 = 0; k0 < K; k0 += 16) {
#pragma unroll
        for (int l = 0; l < 2; l++) {
            int idx4 = tid + l * 256;
            int row = idx4 >> 2, kp = (idx4 & 3) * 4;
            float4 v = *(const float4*)(A + (size_t)row * K + k0 + kp);
            sA[row][kp+0]=v.x; sA[row][kp+1]=v.y; sA[row][kp+2]=v.z; sA[row][kp+3]=v.w;
        }
        {
            int col = tid >> 2, kp = (tid & 3) * 4;
            float4 v = make_float4(0.f,0.f,0.f,0.f);
            if (n0 + col < N) v = *(const float4*)(W + (size_t)(n0+col) * K + k0 + kp);
            sB[col][kp+0]=v.x; sB[col][kp+1]=v.y; sB[col][kp+2]=v.z; sB[col][kp+3]=v.w;
        }
        __syncthreads();
#pragma unroll
        for (int kk = 0; kk < 16; kk++) {
            float a[8], bv[4];
#pragma unroll
            for (int i = 0; i < 8; i++) a[i] = sA[rb+i][kk];
#pragma unroll
            for (int j = 0; j < 4; j++) bv[j] = sB[cb+j][kk];
#pragma unroll
            for (int i = 0; i < 8; i++)
#pragma unroll
                for (int j = 0; j < 4; j++) acc[i][j] = fmaf(a[i], bv[j], acc[i][j]);
        }
        __syncthreads();
    }
#pragma unroll
    for (int i = 0; i < 8; i++)
#pragma unroll
        for (int j = 0; j < 4; j++) {
            int c = n0 + cb + j;
            if (c < N) C[(size_t)(rb+i) * N + c] = acc[i][j] + bias[c];
        }
}

// both gate GEMMs in one launch: y=0 -> gi, y=1 -> gh
__global__ void k_gates(const float* __restrict__ W_ih, const float* __restrict__ b_ih,
                        const float* __restrict__ W_hh, const float* __restrict__ b_hh,
                        const float* __restrict__ prev) {
    if (blockIdx.y == 0) gemm128_body(g_gru_in, W_ih, b_ih, g_gi, G3, KIN);
    else                 gemm128_body(prev,     W_hh, b_hh, g_gh, G3, HH);
}

// ---------------- K2: GRU gate fusion --------------------------------------
__global__ void k_gru(const float* __restrict__ hprev, float* __restrict__ out_dh) {
    int b = blockIdx.x, j = threadIdx.x;
    const float* gi = g_gi + b * G3;
    const float* gh = g_gh + b * G3;
    float r  = 1.f / (1.f + expf(-(gi[j] + gh[j])));
    float z  = 1.f / (1.f + expf(-(gi[HH+j] + gh[HH+j])));
    float n  = tanhf(gi[2*HH+j] + r * gh[2*HH+j]);
    float h  = hprev[b * HH + j];
    float dh = (1.f - z) * n + z * h;
    g_dh[b*HH+j]   = dh;
    out_dh[b*HH+j] = dh;
}

// ---------------- big fused tensor-core kernel ------------------------------
// blocks [0,393): score_g GEMM, tile 128x128, K=256
// blocks [393,793): enc GEMM 64 rows x 256 cols, K=512, fused tanh/dot/tanh/mask
struct SmemG { uint32_t sA[128][SPAD]; uint32_t sW[128][SPAD]; };
struct SmemE { uint32_t sA[64][SPAD];  uint32_t sW[256][SPAD]; float red[64][4]; };
union SmemU { SmemG g; SmemE e; };

__device__ void big_gemmg(SmemG& sm, int bx,
                          const float* __restrict__ W,
                          const float* __restrict__ bias) {
    int tid = threadIdx.x;
    int wid = tid >> 5, lane = tid & 31;
    int g = lane >> 2, t = lane & 3;
    int n0 = bx * 128;
    int wm = (wid & 3) * 32;
    int wn = (wid >> 2) * 64;
    const float* A = g_dh;
    float c[2][8][4];
#pragma unroll
    for (int i = 0; i < 2; i++)
#pragma unroll
        for (int j = 0; j < 8; j++)
#pragma unroll
            for (int q = 0; q < 4; q++) c[i][j][q] = 0.f;

    for (int k0 = 0; k0 < HH; k0 += 32) {
#pragma unroll
        for (int l = 0; l < 4; l++) {
            int f4 = tid + l * 256;
            int row = f4 >> 3, kp = (f4 & 7) * 4;
            float4 v = *(const float4*)(A + (size_t)row * HH + k0 + kp);
            sm.sA[row][kp+0]=f2tf(v.x); sm.sA[row][kp+1]=f2tf(v.y);
            sm.sA[row][kp+2]=f2tf(v.z); sm.sA[row][kp+3]=f2tf(v.w);
        }
#pragma unroll
        for (int l = 0; l < 4; l++) {
            int f4 = tid + l * 256;
            int row = f4 >> 3, kp = (f4 & 7) * 4;
            float4 v = make_float4(0.f,0.f,0.f,0.f);
            if (n0 + row < VV) v = *(const float4*)(W + (size_t)(n0+row) * HH + k0 + kp);
            sm.sW[row][kp+0]=f2tf(v.x); sm.sW[row][kp+1]=f2tf(v.y);
            sm.sW[row][kp+2]=f2tf(v.z); sm.sW[row][kp+3]=f2tf(v.w);
        }
        __syncthreads();
#pragma unroll
        for (int kk = 0; kk < 4; kk++) {
            int kb = kk * 8;
            uint32_t a[2][4];
#pragma unroll
            for (int i = 0; i < 2; i++) {
                int r = wm + i*16 + g;
                a[i][0] = sm.sA[r][kb+t];     a[i][1] = sm.sA[r+8][kb+t];
                a[i][2] = sm.sA[r][kb+t+4];   a[i][3] = sm.sA[r+8][kb+t+4];
            }
            uint32_t bf[8][2];
#pragma unroll
            for (int j = 0; j < 8; j++) {
                int n = wn + j*8 + g;
                bf[j][0] = sm.sW[n][kb+t]; bf[j][1] = sm.sW[n][kb+t+4];
            }
#pragma unroll
            for (int i = 0; i < 2; i++)
#pragma unroll
                for (int j = 0; j < 8; j++) mma8(c[i][j], a[i], bf[j]);
        }
        __syncthreads();
    }
#pragma unroll
    for (int i = 0; i < 2; i++) {
        int r = wm + i*16 + g;
#pragma unroll
        for (int j = 0; j < 8; j++) {
            int col = n0 + wn + j*8 + 2*t;
            if (col < VV) {
                float b0 = bias[col];
                g_score[(size_t)r*VV + col]     = c[i][j][0] + b0;
                g_score[(size_t)(r+8)*VV + col] = c[i][j][2] + b0;
                if (col + 1 < VV) {
                    float b1 = bias[col+1];
                    g_score[(size_t)r*VV + col+1]     = c[i][j][1] + b1;
                    g_score[(size_t)(r+8)*VV + col+1] = c[i][j][3] + b1;
                }
            }
        }
    }
}

__device__ void big_enc(SmemE& sm, int bx,
                        const float* __restrict__ EO,
                        const float* __restrict__ Wc,
                        const float* __restrict__ cbias,
                        const int* __restrict__ idxs) {
    int tid = threadIdx.x;
    int wid = tid >> 5, lane = tid & 31;
    int g = lane >> 2, t = lane & 3;
    int r0 = bx * 64;
    int wm = (wid & 1) * 32;
    int wn = (wid >> 1) * 64;
    float c[2][8][4];
#pragma unroll
    for (int i = 0; i < 2; i++)
#pragma unroll
        for (int j = 0; j < 8; j++)
#pragma unroll
            for (int q = 0; q < 4; q++) c[i][j][q] = 0.f;

    for (int k0 = 0; k0 < 2*HH; k0 += 32) {
#pragma unroll
        for (int l = 0; l < 2; l++) {
            int f4 = tid + l * 256;
            int row = f4 >> 3, kp = (f4 & 7) * 4;
            float4 v = *(const float4*)(EO + (size_t)(r0+row) * (2*HH) + k0 + kp);
            sm.sA[row][kp+0]=f2tf(v.x); sm.sA[row][kp+1]=f2tf(v.y);
            sm.sA[row][kp+2]=f2tf(v.z); sm.sA[row][kp+3]=f2tf(v.w);
        }
#pragma unroll
        for (int l = 0; l < 8; l++) {
            int f4 = tid + l * 256;
            int row = f4 >> 3, kp = (f4 & 7) * 4;
            float4 v = *(const float4*)(Wc + (size_t)row * (2*HH) + k0 + kp);
            sm.sW[row][kp+0]=f2tf(v.x); sm.sW[row][kp+1]=f2tf(v.y);
            sm.sW[row][kp+2]=f2tf(v.z); sm.sW[row][kp+3]=f2tf(v.w);
        }
        __syncthreads();
#pragma unroll
        for (int kk = 0; kk < 4; kk++) {
            int kb = kk * 8;
            uint32_t a[2][4];
#pragma unroll
            for (int i = 0; i < 2; i++) {
                int r = wm + i*16 + g;
                a[i][0] = sm.sA[r][kb+t];     a[i][1] = sm.sA[r+8][kb+t];
                a[i][2] = sm.sA[r][kb+t+4];   a[i][3] = sm.sA[r+8][kb+t+4];
            }
            uint32_t bf[8][2];
#pragma unroll
            for (int j = 0; j < 8; j++) {
                int n = wn + j*8 + g;
                bf[j][0] = sm.sW[n][kb+t]; bf[j][1] = sm.sW[n][kb+t+4];
            }
#pragma unroll
            for (int i = 0; i < 2; i++)
#pragma unroll
                for (int j = 0; j < 8; j++) mma8(c[i][j], a[i], bf[j]);
        }
        __syncthreads();
    }
    // epilogue: rowsum_n tanh(c + bias[n]) * dh[b][n]
    float rs[2][2] = {{0.f,0.f},{0.f,0.f}};
#pragma unroll
    for (int i = 0; i < 2; i++) {
        int grow = r0 + wm + i*16 + g;
        int b0r = grow / TT;
        int b1r = (grow + 8) / TT;
#pragma unroll
        for (int j = 0; j < 8; j++) {
            int col = wn + j*8 + 2*t;
            float bi0 = cbias[col], bi1 = cbias[col+1];
            rs[i][0] += tanhf(c[i][j][0]+bi0) * g_dh[b0r*HH+col]
                      + tanhf(c[i][j][1]+bi1) * g_dh[b0r*HH+col+1];
            rs[i][1] += tanhf(c[i][j][2]+bi0) * g_dh[b1r*HH+col]
                      + tanhf(c[i][j][3]+bi1) * g_dh[b1r*HH+col+1];
        }
    }
#pragma unroll
    for (int i = 0; i < 2; i++)
#pragma unroll
        for (int h = 0; h < 2; h++) {
            float v = rs[i][h];
            v += __shfl_xor_sync(0xffffffffu, v, 1);
            v += __shfl_xor_sync(0xffffffffu, v, 2);
            if (t == 0) sm.red[wm + i*16 + h*8 + g][wid >> 1] = v;
        }
    __syncthreads();
    if (tid < 64) {
        float tot = sm.red[tid][0] + sm.red[tid][1] + sm.red[tid][2] + sm.red[tid][3];
        float v = tanhf(tot);
        int grow = r0 + tid;
        if (idxs[grow] == 0) v -= 10000.f;
        g_scraw[grow] = v;
    }
}

#define NBG 393   // ceil(50257/128)
#define NBE 400   // 25600/64

__global__ void __launch_bounds__(256) k_big(
        const float* __restrict__ Wg, const float* __restrict__ gbias,
        const float* __restrict__ EO, const float* __restrict__ Wc,
        const float* __restrict__ cbias, const int* __restrict__ idxs) {
    __shared__ SmemU sm;
    int bx = blockIdx.x;
    if (bx < NBG) big_gemmg(sm.g, bx, Wg, gbias);
    else          big_enc(sm.e, bx - NBG, EO, Wc, cbias, idxs);
}

// ---------------- softmax over [score_g | score_c] + output ----------------
__global__ void k_softmax(const int* __restrict__ idxs, float* __restrict__ out) {
    int b = blockIdx.x, tid = threadIdx.x;    // 512 threads
    __shared__ float sred[512];
    const float* sg = g_score + (size_t)b * VV;
    const float* sc = g_scraw + b * TT;
    float m = -1e30f;
    for (int v = tid; v < VV; v += 512) m = fmaxf(m, sg[v]);
    for (int t = tid; t < TT; t += 512) m = fmaxf(m, sc[t]);
    sred[tid] = m; __syncthreads();
    for (int s = 256; s > 0; s >>= 1) {
        if (tid < s) sred[tid] = fmaxf(sred[tid], sred[tid + s]);
        __syncthreads();
    }
    m = sred[0]; __syncthreads();
    float sum = 0.f;
    for (int v = tid; v < VV; v += 512) sum += __expf(sg[v] - m);
    for (int t = tid; t < TT; t += 512) sum += __expf(sc[t] - m);
    sred[tid] = sum; __syncthreads();
    for (int s = 256; s > 0; s >>= 1) {
        if (tid < s) sred[tid] += sred[tid + s];
        __syncthreads();
    }
    float inv = 1.f / sred[0]; __syncthreads();
    float* orow = out + (size_t)b * VO;
    for (int v = tid; v < VV; v += 512) orow[v] = __expf(sg[v] - m) * inv;
    for (int j = tid; j < NOOV; j += 512) orow[VV + j] = 1e-4f;
    for (int t = tid; t < TT; t += 512) g_probc[b * TT + t] = __expf(sc[t] - m) * inv;
    __syncthreads();
    for (int t = tid; t < TT; t += 512)
        atomicAdd(&orow[idxs[b * TT + t]], g_probc[b * TT + t]);
}

// ---------------- selective_read (sparse match) ------------------------------
__global__ void k_selread(const int* __restrict__ idxs, const int* __restrict__ dec,
                          const float* __restrict__ EO, float* __restrict__ out_sr) {
    int b = blockIdx.x, tid = threadIdx.x;
    __shared__ int mt[TT];
    __shared__ int cnt;
    if (tid == 0) cnt = 0;
    __syncthreads();
    int d = dec[b];
    for (int t = tid; t < TT; t += 256)
        if (idxs[b * TT + t] == d) { int p = atomicAdd(&cnt, 1); mt[p] = t; }
    __syncthreads();
    int n = cnt;
    float scale = (n > 1) ? 1.f / (float)n : 1.f;
    for (int e = tid; e < 2 * HH; e += 256) {
        float acc = 0.f;
        for (int k = 0; k < n; k++) {
            int t = mt[k];
            acc += g_probc[b * TT + t] * scale *
                   EO[((size_t)b * TT + t) * (2 * HH) + e];
        }
        out_sr[b * 2 * HH + e] = acc;
    }
}

// ---------------- launch ----------------------------------------------------
extern "C" void kernel_launch(void* const* d_in, const int* in_sizes, int n_in,
                              void* d_out, int out_size) {
    const int*   dec  = (const int*)d_in[0];
    const float* EO   = (const float*)d_in[1];
    const int*   idxs = (const int*)d_in[2];
    const float* prev = (const float*)d_in[3];
    const float* sr   = (const float*)d_in[4];
    int off = (n_in >= 17 && in_sizes[5] == 1) ? 1 : 0;
    const float* emb  = (const float*)d_in[5 + off];
    const float* W_ih = (const float*)d_in[6 + off];
    const float* W_hh = (const float*)d_in[7 + off];
    const float* b_ih = (const float*)d_in[8 + off];
    const float* b_hh = (const float*)d_in[9 + off];
    const float* Wg_w = (const float*)d_in[12 + off];
    const float* Wg_b = (const float*)d_in[13 + off];
    const float* Wc_w = (const float*)d_in[14 + off];
    const float* Wc_b = (const float*)d_in[15 + off];

    float* out    = (float*)d_out;
    float* out_dh = out + (size_t)BB * VO;
    float* out_sr = out_dh + (size_t)BB * HH;

    k_gruin<<<BB, KIN>>>(dec, sr, emb);
    k_gates<<<dim3(G3 / 64, 2), 256>>>(W_ih, b_ih, W_hh, b_hh, prev);
    k_gru<<<BB, HH>>>(prev, out_dh);
    k_big<<<NBG + NBE, 256>>>(Wg_w, Wg_b, EO, Wc_w, Wc_b, idxs);
    k_softmax<<<BB, 512>>>(idxs, out);
    k_selread<<<BB, 256>>>(idxs, dec, EO, out_sr);
}

// round 3
// speedup vs baseline: 2.8948x; 1.1961x over previous
#include <cuda_runtime.h>
#include <math.h>
#include <stdint.h>

#define BB   128
#define TT   200
#define VV   50257
#define VVP  50260          // padded row stride for g_score (16B aligned rows)
#define HH   256
#define EE   128
#define NOOV 50
#define KIN  640
#define G3   768
#define VO   (VV + NOOV)
#define BT   (BB * TT)
#define SPAD 36

#define NBG  197            // ceil(50257/256) score_g tiles (N=256)
#define NBE  200            // 25600/128 enc tiles (M rows = 128)

// stage layout (words): A 128*36, W 256*36
#define AW   (128 * SPAD)
#define WW   (256 * SPAD)
#define STG_W (AW + WW)     // 13824 words per stage
#define DYN_BYTES (2 * STG_W * 4)   // 110592

// ---------------- scratch ----------------------------------------------
__device__ float g_gru_in[BB * KIN];
__device__ float g_gi[BB * G3];
__device__ float g_gh[BB * G3];
__device__ float g_dh[BB * HH];
__device__ float g_score[BB * VVP];
__device__ float g_scraw[BT];
__device__ float g_pmax[BB * NBG];
__device__ float g_psum[BB * NBG];
__device__ float g_M[BB];
__device__ float g_invS[BB];

// ---------------- helpers ------------------------------------------------
__device__ __forceinline__ void mma8(float* c, const uint32_t* a, const uint32_t* b) {
    asm volatile(
        "mma.sync.aligned.m16n8k8.row.col.f32.tf32.tf32.f32 "
        "{%0,%1,%2,%3}, {%4,%5,%6,%7}, {%8,%9}, {%0,%1,%2,%3};\n"
        : "+f"(c[0]), "+f"(c[1]), "+f"(c[2]), "+f"(c[3])
        : "r"(a[0]), "r"(a[1]), "r"(a[2]), "r"(a[3]), "r"(b[0]), "r"(b[1]));
}
__device__ __forceinline__ void cpa16(uint32_t saddr, const float* g, int srcsz) {
    asm volatile("cp.async.ca.shared.global [%0], [%1], 16, %2;\n"
                 :: "r"(saddr), "l"(g), "r"(srcsz));
}
__device__ __forceinline__ void cp_commit() { asm volatile("cp.async.commit_group;\n"); }
__device__ __forceinline__ void cp_wait1()  { asm volatile("cp.async.wait_group 1;\n"); }
// online softmax merge: (m,s) <- merge((m,s),(om,os))
__device__ __forceinline__ void osm(float& m, float& s, float om, float os) {
    float M = fmaxf(m, om);
    s = s * __expf(m - M) + os * __expf(om - M);
    m = M;
}

// ---------------- K0: gru_in = [selective_read | emb[dec]] ----------------
__global__ void k_gruin(const int* __restrict__ dec,
                        const float* __restrict__ sr,
                        const float* __restrict__ emb) {
    int b = blockIdx.x, i = threadIdx.x;
    float v;
    if (i < 2 * HH) v = sr[b * 2 * HH + i];
    else            v = emb[(size_t)dec[b] * EE + (i - 2 * HH)];
    g_gru_in[b * KIN + i] = v;
}

// ---------------- SIMT GEMM for the small GRU gate GEMMs ------------------
__device__ void gemm128_body(const float* __restrict__ A,
                             const float* __restrict__ W,
                             const float* __restrict__ bias,
                             float* __restrict__ C, int N, int K) {
    __shared__ float sA[128][17];
    __shared__ float sB[64][17];
    int tid = threadIdx.x;
    int n0  = blockIdx.x * 64;
    int rb  = (tid >> 4) * 8;
    int cb  = (tid & 15) * 4;
    float acc[8][4];
#pragma unroll
    for (int i = 0; i < 8; i++)
#pragma unroll
        for (int j = 0; j < 4; j++) acc[i][j] = 0.f;
    for (int k0 = 0; k0 < K; k0 += 16) {
#pragma unroll
        for (int l = 0; l < 2; l++) {
            int idx4 = tid + l * 256;
            int row = idx4 >> 2, kp = (idx4 & 3) * 4;
            float4 v = *(const float4*)(A + (size_t)row * K + k0 + kp);
            sA[row][kp+0]=v.x; sA[row][kp+1]=v.y; sA[row][kp+2]=v.z; sA[row][kp+3]=v.w;
        }
        {
            int col = tid >> 2, kp = (tid & 3) * 4;
            float4 v = make_float4(0.f,0.f,0.f,0.f);
            if (n0 + col < N) v = *(const float4*)(W + (size_t)(n0+col) * K + k0 + kp);
            sB[col][kp+0]=v.x; sB[col][kp+1]=v.y; sB[col][kp+2]=v.z; sB[col][kp+3]=v.w;
        }
        __syncthreads();
#pragma unroll
        for (int kk = 0; kk < 16; kk++) {
            float a[8], bv[4];
#pragma unroll
            for (int i = 0; i < 8; i++) a[i] = sA[rb+i][kk];
#pragma unroll
            for (int j = 0; j < 4; j++) bv[j] = sB[cb+j][kk];
#pragma unroll
            for (int i = 0; i < 8; i++)
#pragma unroll
                for (int j = 0; j < 4; j++) acc[i][j] = fmaf(a[i], bv[j], acc[i][j]);
        }
        __syncthreads();
    }
#pragma unroll
    for (int i = 0; i < 8; i++)
#pragma unroll
        for (int j = 0; j < 4; j++) {
            int c = n0 + cb + j;
            if (c < N) C[(size_t)(rb+i) * N + c] = acc[i][j] + bias[c];
        }
}

__global__ void k_gates(const float* __restrict__ W_ih, const float* __restrict__ b_ih,
                        const float* __restrict__ W_hh, const float* __restrict__ b_hh,
                        const float* __restrict__ prev) {
    if (blockIdx.y == 0) gemm128_body(g_gru_in, W_ih, b_ih, g_gi, G3, KIN);
    else                 gemm128_body(prev,     W_hh, b_hh, g_gh, G3, HH);
}

// ---------------- GRU gate fusion -----------------------------------------
__global__ void k_gru(const float* __restrict__ hprev, float* __restrict__ out_dh) {
    int b = blockIdx.x, j = threadIdx.x;
    const float* gi = g_gi + b * G3;
    const float* gh = g_gh + b * G3;
    float r  = 1.f / (1.f + expf(-(gi[j] + gh[j])));
    float z  = 1.f / (1.f + expf(-(gi[HH+j] + gh[HH+j])));
    float n  = tanhf(gi[2*HH+j] + r * gh[2*HH+j]);
    float h  = hprev[b * HH + j];
    float dh = (1.f - z) * n + z * h;
    g_dh[b*HH+j]   = dh;
    out_dh[b*HH+j] = dh;
}

// ---------------- big fused tensor-core kernel ------------------------------
// unified tile: M=128, N=256, k-chunk 32; 512 threads, 16 warps (4x4),
// warp tile 32x64. cp.async double-buffered. fp32 bits used directly as tf32.

__device__ __forceinline__ void load_stage(uint32_t sbase, int stage,
        const float* __restrict__ A, int lda,
        const float* __restrict__ W, int ldw, int wvalid,
        int k0, int tid) {
    uint32_t s0 = sbase + (uint32_t)stage * (STG_W * 4);
#pragma unroll
    for (int l = 0; l < 6; l++) {
        int idx = tid + l * 512;
        if (idx < 1024) {
            int row = idx >> 3, kp = (idx & 7) * 4;
            cpa16(s0 + (row * SPAD + kp) * 4, A + (size_t)row * lda + k0 + kp, 16);
        } else {
            int w   = idx - 1024;
            int row = w >> 3, kp = (w & 7) * 4;
            int ok  = row < wvalid;
            const float* src = W + (size_t)(ok ? row : 0) * ldw + k0 + kp;
            cpa16(s0 + (AW + row * SPAD + kp) * 4, src, ok ? 16 : 0);
        }
    }
}

__device__ __forceinline__ void compute_stage(const uint32_t* __restrict__ sm,
        int wm, int wn, int g, int t, float c[2][8][4]) {
    const uint32_t* sA = sm;
    const uint32_t* sW = sm + AW;
#pragma unroll
    for (int kk = 0; kk < 4; kk++) {
        int kb = kk * 8;
        uint32_t a[2][4];
#pragma unroll
        for (int i = 0; i < 2; i++) {
            int r = wm + i * 16 + g;
            a[i][0] = sA[r * SPAD + kb + t];       a[i][1] = sA[(r + 8) * SPAD + kb + t];
            a[i][2] = sA[r * SPAD + kb + t + 4];   a[i][3] = sA[(r + 8) * SPAD + kb + t + 4];
        }
        uint32_t bf[8][2];
#pragma unroll
        for (int j = 0; j < 8; j++) {
            int n = wn + j * 8 + g;
            bf[j][0] = sW[n * SPAD + kb + t];  bf[j][1] = sW[n * SPAD + kb + t + 4];
        }
#pragma unroll
        for (int i = 0; i < 2; i++)
#pragma unroll
            for (int j = 0; j < 8; j++) mma8(c[i][j], a[i], bf[j]);
    }
}

__global__ void __launch_bounds__(512, 1) k_big(
        const float* __restrict__ Wg, const float* __restrict__ gbias,
        const float* __restrict__ EO, const float* __restrict__ Wc,
        const float* __restrict__ cbias, const int* __restrict__ idxs) {
    extern __shared__ uint32_t dyn[];
    uint32_t sbase = (uint32_t)__cvta_generic_to_shared(dyn);
    int tid = threadIdx.x, wid = tid >> 5, lane = tid & 31;
    int g = lane >> 2, t = lane & 3;
    int wm = (wid & 3) * 32, wn = (wid >> 2) * 64;
    int bx = blockIdx.x;
    bool isg = bx < NBG;

    const float* A; const float* W;
    int lda, ldw, NIT, wvalid;
    if (isg) {
        A = g_dh; lda = HH;
        W = Wg + (size_t)bx * 256 * HH; ldw = HH;
        NIT = HH / 32;  wvalid = VV - bx * 256; if (wvalid > 256) wvalid = 256;
    } else {
        int r0 = (bx - NBG) * 128;
        A = EO + (size_t)r0 * (2 * HH); lda = 2 * HH;
        W = Wc; ldw = 2 * HH;
        NIT = (2 * HH) / 32; wvalid = 256;
    }

    float c[2][8][4];
#pragma unroll
    for (int i = 0; i < 2; i++)
#pragma unroll
        for (int j = 0; j < 8; j++)
#pragma unroll
            for (int q = 0; q < 4; q++) c[i][j][q] = 0.f;

    load_stage(sbase, 0, A, lda, W, ldw, wvalid, 0,  tid); cp_commit();
    load_stage(sbase, 1, A, lda, W, ldw, wvalid, 32, tid); cp_commit();

    for (int it = 0; it < NIT; it++) {
        cp_wait1();
        __syncthreads();
        compute_stage(dyn + (it & 1) * STG_W, wm, wn, g, t, c);
        __syncthreads();
        if (it + 2 < NIT)
            load_stage(sbase, it & 1, A, lda, W, ldw, wvalid, (it + 2) * 32, tid);
        cp_commit();
    }

    if (isg) {
        // ---- epilogue: write score_g (+bias) and per-tile online (max,sumexp) --
        int n0 = bx * 256;
        float lm[2][2], ls[2][2];
#pragma unroll
        for (int i = 0; i < 2; i++)
#pragma unroll
            for (int h = 0; h < 2; h++) { lm[i][h] = -1e30f; ls[i][h] = 0.f; }
#pragma unroll
        for (int i = 0; i < 2; i++) {
            int r = wm + i * 16 + g;
#pragma unroll
            for (int j = 0; j < 8; j++) {
                int col = n0 + wn + j * 8 + 2 * t;
                if (col < VV) {
                    float b0 = gbias[col];
                    float v0 = c[i][j][0] + b0, v2 = c[i][j][2] + b0;
                    g_score[(size_t)r * VVP + col]       = v0;
                    g_score[(size_t)(r + 8) * VVP + col] = v2;
                    lm[i][0] = fmaxf(lm[i][0], v0); lm[i][1] = fmaxf(lm[i][1], v2);
                    if (col + 1 < VV) {
                        float b1 = gbias[col + 1];
                        float v1 = c[i][j][1] + b1, v3 = c[i][j][3] + b1;
                        g_score[(size_t)r * VVP + col + 1]       = v1;
                        g_score[(size_t)(r + 8) * VVP + col + 1] = v3;
                        lm[i][0] = fmaxf(lm[i][0], v1); lm[i][1] = fmaxf(lm[i][1], v3);
                    }
                }
            }
        }
#pragma unroll
        for (int i = 0; i < 2; i++) {
#pragma unroll
            for (int j = 0; j < 8; j++) {
                int col = n0 + wn + j * 8 + 2 * t;
                if (col < VV) {
                    float b0 = gbias[col];
                    ls[i][0] += __expf(c[i][j][0] + b0 - lm[i][0]);
                    ls[i][1] += __expf(c[i][j][2] + b0 - lm[i][1]);
                    if (col + 1 < VV) {
                        float b1 = gbias[col + 1];
                        ls[i][0] += __expf(c[i][j][1] + b1 - lm[i][0]);
                        ls[i][1] += __expf(c[i][j][3] + b1 - lm[i][1]);
                    }
                }
            }
        }
        __syncthreads();               // smem buffers now reusable
        float* redm = (float*)dyn;     // [128][4]
        float* reds = redm + 512;
#pragma unroll
        for (int i = 0; i < 2; i++)
#pragma unroll
            for (int h = 0; h < 2; h++) {
                float m = lm[i][h], s = ls[i][h];
#pragma unroll
                for (int off = 1; off <= 2; off <<= 1) {
                    float om = __shfl_xor_sync(0xffffffffu, m, off);
                    float os = __shfl_xor_sync(0xffffffffu, s, off);
                    osm(m, s, om, os);
                }
                if (t == 0) {
                    int row = wm + i * 16 + h * 8 + g;
                    redm[row * 4 + (wid >> 2)] = m;
                    reds[row * 4 + (wid >> 2)] = s;
                }
            }
        __syncthreads();
        if (tid < 128) {
            float m = redm[tid * 4], s = reds[tid * 4];
            osm(m, s, redm[tid * 4 + 1], reds[tid * 4 + 1]);
            osm(m, s, redm[tid * 4 + 2], reds[tid * 4 + 2]);
            osm(m, s, redm[tid * 4 + 3], reds[tid * 4 + 3]);
            g_pmax[tid * NBG + bx] = m;
            g_psum[tid * NBG + bx] = s;
        }
    } else {
        // ---- epilogue: score_c = tanh(rowsum tanh(c+bias)*dh) + mask ----------
        int r0 = (bx - NBG) * 128;
        float rs[2][2] = {{0.f, 0.f}, {0.f, 0.f}};
#pragma unroll
        for (int i = 0; i < 2; i++) {
            int grow = r0 + wm + i * 16 + g;
            int b0r = grow / TT;
            int b1r = (grow + 8) / TT;
#pragma unroll
            for (int j = 0; j < 8; j++) {
                int col = wn + j * 8 + 2 * t;
                float bi0 = cbias[col], bi1 = cbias[col + 1];
                rs[i][0] += tanhf(c[i][j][0] + bi0) * g_dh[b0r * HH + col]
                          + tanhf(c[i][j][1] + bi1) * g_dh[b0r * HH + col + 1];
                rs[i][1] += tanhf(c[i][j][2] + bi0) * g_dh[b1r * HH + col]
                          + tanhf(c[i][j][3] + bi1) * g_dh[b1r * HH + col + 1];
            }
        }
        __syncthreads();
        float* red = (float*)dyn;      // [128][4]
#pragma unroll
        for (int i = 0; i < 2; i++)
#pragma unroll
            for (int h = 0; h < 2; h++) {
                float v = rs[i][h];
                v += __shfl_xor_sync(0xffffffffu, v, 1);
                v += __shfl_xor_sync(0xffffffffu, v, 2);
                if (t == 0) red[(wm + i * 16 + h * 8 + g) * 4 + (wid >> 2)] = v;
            }
        __syncthreads();
        if (tid < 128) {
            float tot = red[tid * 4] + red[tid * 4 + 1] + red[tid * 4 + 2] + red[tid * 4 + 3];
            float v = tanhf(tot);
            int grow = r0 + tid;
            if (idxs[grow] == 0) v -= 10000.f;
            g_scraw[grow] = v;
        }
    }
}

// ---------------- merge partials -> row (M, 1/S) ---------------------------
__global__ void k_merge() {
    int b = blockIdx.x, tid = threadIdx.x;   // 256 threads
    __shared__ float sm_[256], ss_[256];
    float m = -1e30f, s = 0.f;
    for (int i = tid; i < NBG; i += 256) osm(m, s, g_pmax[b * NBG + i], g_psum[b * NBG + i]);
    for (int t2 = tid; t2 < TT; t2 += 256) osm(m, s, g_scraw[b * TT + t2], 1.f);
    sm_[tid] = m; ss_[tid] = s; __syncthreads();
    for (int st = 128; st > 0; st >>= 1) {
        if (tid < st) {
            float m2 = sm_[tid], s2 = ss_[tid];
            osm(m2, s2, sm_[tid + st], ss_[tid + st]);
            sm_[tid] = m2; ss_[tid] = s2;
        }
        __syncthreads();
    }
    if (tid == 0) { g_M[b] = sm_[0]; g_invS[b] = 1.f / ss_[0]; }
}

// ---------------- normalize score_g -> out ---------------------------------
__global__ void k_out(float* __restrict__ out) {
    int b = blockIdx.y;
    int c0 = blockIdx.x * 2048 + threadIdx.x * 4;
    float M = g_M[b], inv = g_invS[b];
    const float* sg = g_score + (size_t)b * VVP;
    float* orow = out + (size_t)b * VO;
    if (c0 + 3 < VV) {
        float4 v = *(const float4*)(sg + c0);
        orow[c0 + 0] = __expf(v.x - M) * inv;
        orow[c0 + 1] = __expf(v.y - M) * inv;
        orow[c0 + 2] = __expf(v.z - M) * inv;
        orow[c0 + 3] = __expf(v.w - M) * inv;
    } else {
        for (int c = c0; c < VV && c < c0 + 4; c++)
            orow[c] = __expf(sg[c] - M) * inv;
    }
}

// ---------------- tail: probc + OOV + scatter + selective_read -------------
__global__ void k_tail(const int* __restrict__ idxs, const int* __restrict__ dec,
                       const float* __restrict__ EO, float* __restrict__ out,
                       float* __restrict__ out_sr) {
    int b = blockIdx.x, tid = threadIdx.x;   // 256 threads
    __shared__ float pc[TT];
    __shared__ int mt[TT];
    __shared__ int cnt;
    float M = g_M[b], inv = g_invS[b];
    float* orow = out + (size_t)b * VO;
    if (tid == 0) cnt = 0;
    for (int t2 = tid; t2 < TT; t2 += 256)
        pc[t2] = __expf(g_scraw[b * TT + t2] - M) * inv;
    if (tid < NOOV) orow[VV + tid] = 1e-4f;
    __syncthreads();
    int d = dec[b];
    for (int t2 = tid; t2 < TT; t2 += 256) {
        atomicAdd(&orow[idxs[b * TT + t2]], pc[t2]);
        if (idxs[b * TT + t2] == d) { int p = atomicAdd(&cnt, 1); mt[p] = t2; }
    }
    __syncthreads();
    int n = cnt;
    float scale = (n > 1) ? 1.f / (float)n : 1.f;
    for (int e = tid; e < 2 * HH; e += 256) {
        float acc = 0.f;
        for (int k = 0; k < n; k++) {
            int t2 = mt[k];
            acc += pc[t2] * scale * EO[((size_t)b * TT + t2) * (2 * HH) + e];
        }
        out_sr[b * 2 * HH + e] = acc;
    }
}

// ---------------- launch ----------------------------------------------------
extern "C" void kernel_launch(void* const* d_in, const int* in_sizes, int n_in,
                              void* d_out, int out_size) {
    const int*   dec  = (const int*)d_in[0];
    const float* EO   = (const float*)d_in[1];
    const int*   idxs = (const int*)d_in[2];
    const float* prev = (const float*)d_in[3];
    const float* sr   = (const float*)d_in[4];
    int off = (n_in >= 17 && in_sizes[5] == 1) ? 1 : 0;
    const float* emb  = (const float*)d_in[5 + off];
    const float* W_ih = (const float*)d_in[6 + off];
    const float* W_hh = (const float*)d_in[7 + off];
    const float* b_ih = (const float*)d_in[8 + off];
    const float* b_hh = (const float*)d_in[9 + off];
    const float* Wg_w = (const float*)d_in[12 + off];
    const float* Wg_b = (const float*)d_in[13 + off];
    const float* Wc_w = (const float*)d_in[14 + off];
    const float* Wc_b = (const float*)d_in[15 + off];

    float* out    = (float*)d_out;
    float* out_dh = out + (size_t)BB * VO;
    float* out_sr = out_dh + (size_t)BB * HH;

    cudaFuncSetAttribute(k_big, cudaFuncAttributeMaxDynamicSharedMemorySize, DYN_BYTES);

    k_gruin<<<BB, KIN>>>(dec, sr, emb);
    k_gates<<<dim3(G3 / 64, 2), 256>>>(W_ih, b_ih, W_hh, b_hh, prev);
    k_gru<<<BB, HH>>>(prev, out_dh);
    k_big<<<NBG + NBE, 512, DYN_BYTES>>>(Wg_w, Wg_b, EO, Wc_w, Wc_b, idxs);
    k_merge<<<BB, 256>>>();
    k_out<<<dim3((VV + 2047) / 2048, BB), 512>>>(out);
    k_tail<<<BB, 256>>>(idxs, dec, EO, out, out_sr);
}

// round 4
// speedup vs baseline: 3.3418x; 1.1544x over previous
#include <cuda_runtime.h>
#include <math.h>
#include <stdint.h>

#define BB   128
#define TT   200
#define VV   50257
#define VVP  50260
#define HH   256
#define EE   128
#define NOOV 50
#define G3   768
#define VO   (VV + NOOV)
#define BT   (BB * TT)
#define SPAD 36

#define NBG  393            // ceil(50257/128): score_g tiles, 128x128
#define NBE  400            // 25600/64: enc tiles, 64x256

// stage word sizes
#define STG_G ((128 + 128) * SPAD)   // 9216 words
#define STG_E ((64 + 256) * SPAD)    // 11520 words
#define DYN_BIG   (2 * STG_E * 4)    // 92160 B
#define DYN_GATES (2 * STG_G * 4)    // 73728 B

// ---------------- scratch ----------------------------------------------
__device__ float g_gi[BB * G3];
__device__ float g_gh[BB * G3];
__device__ float g_dh[BB * HH];
__device__ float g_score[BB * VVP];
__device__ float g_scraw[BT];
__device__ float g_pmax[BB * NBG];
__device__ float g_psum[BB * NBG];
__device__ float g_M[BB];
__device__ float g_invS[BB];

// ---------------- helpers ------------------------------------------------
__device__ __forceinline__ void mma8(float* c, const uint32_t* a, const uint32_t* b) {
    asm volatile(
        "mma.sync.aligned.m16n8k8.row.col.f32.tf32.tf32.f32 "
        "{%0,%1,%2,%3}, {%4,%5,%6,%7}, {%8,%9}, {%0,%1,%2,%3};\n"
        : "+f"(c[0]), "+f"(c[1]), "+f"(c[2]), "+f"(c[3])
        : "r"(a[0]), "r"(a[1]), "r"(a[2]), "r"(a[3]), "r"(b[0]), "r"(b[1]));
}
__device__ __forceinline__ void cpa16(uint32_t saddr, const float* g, int srcsz) {
    asm volatile("cp.async.ca.shared.global [%0], [%1], 16, %2;\n"
                 :: "r"(saddr), "l"(g), "r"(srcsz));
}
__device__ __forceinline__ void cp_commit() { asm volatile("cp.async.commit_group;\n"); }
__device__ __forceinline__ void cp_wait1()  { asm volatile("cp.async.wait_group 1;\n"); }
__device__ __forceinline__ void osm(float& m, float& s, float om, float os) {
    float M = fmaxf(m, om);
    s = s * __expf(m - M) + os * __expf(om - M);
    m = M;
}

// warp-tile 32x64 MMA over one 32-k stage
__device__ __forceinline__ void warp_mma(const uint32_t* __restrict__ sA,
                                         const uint32_t* __restrict__ sW,
                                         int wm, int wn, int g, int t,
                                         float c[2][8][4]) {
#pragma unroll
    for (int kk = 0; kk < 4; kk++) {
        int kb = kk * 8;
        uint32_t a[2][4];
#pragma unroll
        for (int i = 0; i < 2; i++) {
            int r = wm + i * 16 + g;
            a[i][0] = sA[r * SPAD + kb + t];     a[i][1] = sA[(r + 8) * SPAD + kb + t];
            a[i][2] = sA[r * SPAD + kb + t + 4]; a[i][3] = sA[(r + 8) * SPAD + kb + t + 4];
        }
        uint32_t bf[8][2];
#pragma unroll
        for (int j = 0; j < 8; j++) {
            int n = wn + j * 8 + g;
            bf[j][0] = sW[n * SPAD + kb + t]; bf[j][1] = sW[n * SPAD + kb + t + 4];
        }
#pragma unroll
        for (int i = 0; i < 2; i++)
#pragma unroll
            for (int j = 0; j < 8; j++) mma8(c[i][j], a[i], bf[j]);
    }
}

// generic stage loader: nA rows of A, nW rows of W, 32 k-words each, 256 thr
__device__ __forceinline__ void load_stage(uint32_t sbase, int stage, int stgW,
        int nA, const float* __restrict__ A, int lda,
        const float* __restrict__ W, int ldw, int wvalid, int nW,
        int k0, int tid) {
    uint32_t s0 = sbase + (uint32_t)stage * (stgW * 4);
    int aCh = nA * 8;
    int total = aCh + nW * 8;
    for (int idx = tid; idx < total; idx += 256) {
        if (idx < aCh) {
            int row = idx >> 3, kp = (idx & 7) * 4;
            cpa16(s0 + (row * SPAD + kp) * 4, A + (size_t)row * lda + k0 + kp, 16);
        } else {
            int w = idx - aCh;
            int row = w >> 3, kp = (w & 7) * 4;
            int ok = row < wvalid;
            const float* src = W + (size_t)(ok ? row : 0) * ldw + k0 + kp;
            cpa16(s0 + ((nA + row) * SPAD + kp) * 4, src, ok ? 16 : 0);
        }
    }
}

// ---------------- gates kernel: gi = [sr|emb] @ W_ih^T + b, gh = prev @ W_hh^T + b
// 12 blocks: bx<6 -> gi tile (K=640, A = concat), else gh tile (K=256, A=prev)
__global__ void __launch_bounds__(256, 2) k_gates(
        const int* __restrict__ dec, const float* __restrict__ sr,
        const float* __restrict__ emb, const float* __restrict__ prev,
        const float* __restrict__ W_ih, const float* __restrict__ b_ih,
        const float* __restrict__ W_hh, const float* __restrict__ b_hh) {
    extern __shared__ uint32_t dyn[];
    uint32_t sbase = (uint32_t)__cvta_generic_to_shared(dyn);
    int tid = threadIdx.x, wid = tid >> 5, lane = tid & 31;
    int g = lane >> 2, t = lane & 3;
    int wm = (wid & 3) * 32, wn = (wid >> 2) * 64;
    int bx = blockIdx.x;
    bool isGi = bx < 6;
    int n0 = (isGi ? bx : bx - 6) * 128;
    int K  = isGi ? 640 : HH;
    int NIT = K / 32;
    const float* W = (isGi ? W_ih : W_hh) + (size_t)n0 * K;
    const float* bias = isGi ? b_ih : b_hh;
    float* C = isGi ? g_gi : g_gh;

    float c[2][8][4];
#pragma unroll
    for (int i = 0; i < 2; i++)
#pragma unroll
        for (int j = 0; j < 8; j++)
#pragma unroll
            for (int q = 0; q < 4; q++) c[i][j][q] = 0.f;

    // concat-aware A loader for gi
    auto loadA = [&](int stage, int k0) {
        uint32_t s0 = sbase + (uint32_t)stage * (STG_G * 4);
        if (isGi) {
            for (int idx = tid; idx < 1024; idx += 256) {    // 128 rows * 8 chunks
                int row = idx >> 3, kp = (idx & 7) * 4;
                const float* src;
                if (k0 < 512) src = sr + (size_t)row * 512 + k0 + kp;
                else          src = emb + (size_t)dec[row] * EE + (k0 - 512) + kp;
                cpa16(s0 + (row * SPAD + kp) * 4, src, 16);
            }
        } else {
            for (int idx = tid; idx < 1024; idx += 256) {
                int row = idx >> 3, kp = (idx & 7) * 4;
                cpa16(s0 + (row * SPAD + kp) * 4, prev + (size_t)row * HH + k0 + kp, 16);
            }
        }
        // W rows 128
        for (int idx = tid; idx < 1024; idx += 256) {
            int row = idx >> 3, kp = (idx & 7) * 4;
            cpa16(s0 + ((128 + row) * SPAD + kp) * 4, W + (size_t)row * K + k0 + kp, 16);
        }
    };

    loadA(0, 0);  cp_commit();
    loadA(1, 32); cp_commit();
    for (int it = 0; it < NIT; it++) {
        cp_wait1();
        __syncthreads();
        const uint32_t* s = dyn + (it & 1) * STG_G;
        warp_mma(s, s + 128 * SPAD, wm, wn, g, t, c);
        __syncthreads();
        if (it + 2 < NIT) loadA(it & 1, (it + 2) * 32);
        cp_commit();
    }
#pragma unroll
    for (int i = 0; i < 2; i++) {
        int r = wm + i * 16 + g;
#pragma unroll
        for (int j = 0; j < 8; j++) {
            int col = n0 + wn + j * 8 + 2 * t;
            float b0 = bias[col], b1 = bias[col + 1];
            C[(size_t)r * G3 + col]           = c[i][j][0] + b0;
            C[(size_t)r * G3 + col + 1]       = c[i][j][1] + b1;
            C[(size_t)(r + 8) * G3 + col]     = c[i][j][2] + b0;
            C[(size_t)(r + 8) * G3 + col + 1] = c[i][j][3] + b1;
        }
    }
}

// ---------------- GRU gate fusion -----------------------------------------
__global__ void k_gru(const float* __restrict__ hprev, float* __restrict__ out_dh) {
    int b = blockIdx.x, j = threadIdx.x;
    const float* gi = g_gi + b * G3;
    const float* gh = g_gh + b * G3;
    float r  = 1.f / (1.f + expf(-(gi[j] + gh[j])));
    float z  = 1.f / (1.f + expf(-(gi[HH+j] + gh[HH+j])));
    float n  = tanhf(gi[2*HH+j] + r * gh[2*HH+j]);
    float h  = hprev[b * HH + j];
    float dh = (1.f - z) * n + z * h;
    g_dh[b*HH+j]   = dh;
    out_dh[b*HH+j] = dh;
}

// ---------------- big fused tensor-core kernel ------------------------------
// bx < NBG : score_g tile 128x128 (warps 4x2), K=256
// else     : enc tile 64x256 (warps 2x4), K=512, fused tanh/dot/tanh/mask
__global__ void __launch_bounds__(256, 2) k_big(
        const float* __restrict__ Wg, const float* __restrict__ gbias,
        const float* __restrict__ EO, const float* __restrict__ Wc,
        const float* __restrict__ cbias, const int* __restrict__ idxs) {
    extern __shared__ uint32_t dyn[];
    uint32_t sbase = (uint32_t)__cvta_generic_to_shared(dyn);
    int tid = threadIdx.x, wid = tid >> 5, lane = tid & 31;
    int g = lane >> 2, t = lane & 3;
    int bx = blockIdx.x;
    bool isg = bx < NBG;

    int wm, wn, nA, NIT, wvalid, nW, lda, stgW;
    const float* A; const float* W; int ldw;
    if (isg) {
        wm = (wid & 3) * 32; wn = (wid >> 2) * 64;
        A = g_dh; lda = HH; nA = 128;
        W = Wg + (size_t)bx * 128 * HH; ldw = HH; nW = 128;
        wvalid = VV - bx * 128; if (wvalid > 128) wvalid = 128;
        NIT = HH / 32; stgW = STG_G;
    } else {
        wm = (wid & 1) * 32; wn = (wid >> 1) * 64;
        int r0 = (bx - NBG) * 64;
        A = EO + (size_t)r0 * (2 * HH); lda = 2 * HH; nA = 64;
        W = Wc; ldw = 2 * HH; nW = 256; wvalid = 256;
        NIT = (2 * HH) / 32; stgW = STG_E;
    }

    float c[2][8][4];
#pragma unroll
    for (int i = 0; i < 2; i++)
#pragma unroll
        for (int j = 0; j < 8; j++)
#pragma unroll
            for (int q = 0; q < 4; q++) c[i][j][q] = 0.f;

    load_stage(sbase, 0, stgW, nA, A, lda, W, ldw, wvalid, nW, 0,  tid); cp_commit();
    load_stage(sbase, 1, stgW, nA, A, lda, W, ldw, wvalid, nW, 32, tid); cp_commit();

    for (int it = 0; it < NIT; it++) {
        cp_wait1();
        __syncthreads();
        const uint32_t* s = dyn + (it & 1) * stgW;
        warp_mma(s, s + nA * SPAD, wm, wn, g, t, c);
        __syncthreads();
        if (it + 2 < NIT)
            load_stage(sbase, it & 1, stgW, nA, A, lda, W, ldw, wvalid, nW, (it + 2) * 32, tid);
        cp_commit();
    }

    if (isg) {
        int n0 = bx * 128;
        float lm[2][2], ls[2][2];
#pragma unroll
        for (int i = 0; i < 2; i++)
#pragma unroll
            for (int h = 0; h < 2; h++) { lm[i][h] = -1e30f; ls[i][h] = 0.f; }
#pragma unroll
        for (int i = 0; i < 2; i++) {
            int r = wm + i * 16 + g;
#pragma unroll
            for (int j = 0; j < 8; j++) {
                int col = n0 + wn + j * 8 + 2 * t;
                if (col < VV) {
                    float b0 = gbias[col];
                    float v0 = c[i][j][0] + b0, v2 = c[i][j][2] + b0;
                    g_score[(size_t)r * VVP + col]       = v0;
                    g_score[(size_t)(r + 8) * VVP + col] = v2;
                    lm[i][0] = fmaxf(lm[i][0], v0); lm[i][1] = fmaxf(lm[i][1], v2);
                    if (col + 1 < VV) {
                        float b1 = gbias[col + 1];
                        float v1 = c[i][j][1] + b1, v3 = c[i][j][3] + b1;
                        g_score[(size_t)r * VVP + col + 1]       = v1;
                        g_score[(size_t)(r + 8) * VVP + col + 1] = v3;
                        lm[i][0] = fmaxf(lm[i][0], v1); lm[i][1] = fmaxf(lm[i][1], v3);
                    }
                }
            }
        }
#pragma unroll
        for (int i = 0; i < 2; i++)
#pragma unroll
            for (int j = 0; j < 8; j++) {
                int col = n0 + wn + j * 8 + 2 * t;
                if (col < VV) {
                    float b0 = gbias[col];
                    ls[i][0] += __expf(c[i][j][0] + b0 - lm[i][0]);
                    ls[i][1] += __expf(c[i][j][2] + b0 - lm[i][1]);
                    if (col + 1 < VV) {
                        float b1 = gbias[col + 1];
                        ls[i][0] += __expf(c[i][j][1] + b1 - lm[i][0]);
                        ls[i][1] += __expf(c[i][j][3] + b1 - lm[i][1]);
                    }
                }
            }
        __syncthreads();
        float* redm = (float*)dyn;           // [128][2]
        float* reds = redm + 256;
#pragma unroll
        for (int i = 0; i < 2; i++)
#pragma unroll
            for (int h = 0; h < 2; h++) {
                float m = lm[i][h], s = ls[i][h];
#pragma unroll
                for (int off = 1; off <= 2; off <<= 1) {
                    float om = __shfl_xor_sync(0xffffffffu, m, off);
                    float os = __shfl_xor_sync(0xffffffffu, s, off);
                    osm(m, s, om, os);
                }
                if (t == 0) {
                    int row = wm + i * 16 + h * 8 + g;
                    redm[row * 2 + (wid >> 2)] = m;
                    reds[row * 2 + (wid >> 2)] = s;
                }
            }
        __syncthreads();
        if (tid < 128) {
            float m = redm[tid * 2], s = reds[tid * 2];
            osm(m, s, redm[tid * 2 + 1], reds[tid * 2 + 1]);
            g_pmax[tid * NBG + bx] = m;
            g_psum[tid * NBG + bx] = s;
        }
    } else {
        int r0 = (bx - NBG) * 64;
        float rs[2][2] = {{0.f, 0.f}, {0.f, 0.f}};
#pragma unroll
        for (int i = 0; i < 2; i++) {
            int grow = r0 + wm + i * 16 + g;
            int b0r = grow / TT;
            int b1r = (grow + 8) / TT;
#pragma unroll
            for (int j = 0; j < 8; j++) {
                int col = wn + j * 8 + 2 * t;
                float bi0 = cbias[col], bi1 = cbias[col + 1];
                rs[i][0] += tanhf(c[i][j][0] + bi0) * g_dh[b0r * HH + col]
                          + tanhf(c[i][j][1] + bi1) * g_dh[b0r * HH + col + 1];
                rs[i][1] += tanhf(c[i][j][2] + bi0) * g_dh[b1r * HH + col]
                          + tanhf(c[i][j][3] + bi1) * g_dh[b1r * HH + col + 1];
            }
        }
        __syncthreads();
        float* red = (float*)dyn;            // [64][4]
#pragma unroll
        for (int i = 0; i < 2; i++)
#pragma unroll
            for (int h = 0; h < 2; h++) {
                float v = rs[i][h];
                v += __shfl_xor_sync(0xffffffffu, v, 1);
                v += __shfl_xor_sync(0xffffffffu, v, 2);
                if (t == 0) red[(wm + i * 16 + h * 8 + g) * 4 + (wid >> 1)] = v;
            }
        __syncthreads();
        if (tid < 64) {
            float tot = red[tid * 4] + red[tid * 4 + 1] + red[tid * 4 + 2] + red[tid * 4 + 3];
            float v = tanhf(tot);
            int grow = r0 + tid;
            if (idxs[grow] == 0) v -= 10000.f;
            g_scraw[grow] = v;
        }
    }
}

// ---------------- merge partials -> row (M, 1/S) ---------------------------
__global__ void k_merge() {
    int b = blockIdx.x, tid = threadIdx.x;
    __shared__ float sm_[256], ss_[256];
    float m = -1e30f, s = 0.f;
    for (int i = tid; i < NBG; i += 256) osm(m, s, g_pmax[b * NBG + i], g_psum[b * NBG + i]);
    for (int t2 = tid; t2 < TT; t2 += 256) osm(m, s, g_scraw[b * TT + t2], 1.f);
    sm_[tid] = m; ss_[tid] = s; __syncthreads();
    for (int st = 128; st > 0; st >>= 1) {
        if (tid < st) {
            float m2 = sm_[tid], s2 = ss_[tid];
            osm(m2, s2, sm_[tid + st], ss_[tid + st]);
            sm_[tid] = m2; ss_[tid] = s2;
        }
        __syncthreads();
    }
    if (tid == 0) { g_M[b] = sm_[0]; g_invS[b] = 1.f / ss_[0]; }
}

// ---------------- normalize score_g -> out ---------------------------------
__global__ void k_out(float* __restrict__ out) {
    int b = blockIdx.y;
    int c0 = blockIdx.x * 2048 + threadIdx.x * 4;
    float M = g_M[b], inv = g_invS[b];
    const float* sg = g_score + (size_t)b * VVP;
    float* orow = out + (size_t)b * VO;
    if (c0 + 3 < VV) {
        float4 v = *(const float4*)(sg + c0);
        orow[c0 + 0] = __expf(v.x - M) * inv;
        orow[c0 + 1] = __expf(v.y - M) * inv;
        orow[c0 + 2] = __expf(v.z - M) * inv;
        orow[c0 + 3] = __expf(v.w - M) * inv;
    } else {
        for (int c = c0; c < VV && c < c0 + 4; c++)
            orow[c] = __expf(sg[c] - M) * inv;
    }
}

// ---------------- tail: probc + OOV + scatter + selective_read -------------
__global__ void k_tail(const int* __restrict__ idxs, const int* __restrict__ dec,
                       const float* __restrict__ EO, float* __restrict__ out,
                       float* __restrict__ out_sr) {
    int b = blockIdx.x, tid = threadIdx.x;
    __shared__ float pc[TT];
    __shared__ int mt[TT];
    __shared__ int cnt;
    float M = g_M[b], inv = g_invS[b];
    float* orow = out + (size_t)b * VO;
    if (tid == 0) cnt = 0;
    for (int t2 = tid; t2 < TT; t2 += 256)
        pc[t2] = __expf(g_scraw[b * TT + t2] - M) * inv;
    if (tid < NOOV) orow[VV + tid] = 1e-4f;
    __syncthreads();
    int d = dec[b];
    for (int t2 = tid; t2 < TT; t2 += 256) {
        atomicAdd(&orow[idxs[b * TT + t2]], pc[t2]);
        if (idxs[b * TT + t2] == d) { int p = atomicAdd(&cnt, 1); mt[p] = t2; }
    }
    __syncthreads();
    int n = cnt;
    float scale = (n > 1) ? 1.f / (float)n : 1.f;
    for (int e = tid; e < 2 * HH; e += 256) {
        float acc = 0.f;
        for (int k = 0; k < n; k++) {
            int t2 = mt[k];
            acc += pc[t2] * scale * EO[((size_t)b * TT + t2) * (2 * HH) + e];
        }
        out_sr[b * 2 * HH + e] = acc;
    }
}

// ---------------- launch ----------------------------------------------------
extern "C" void kernel_launch(void* const* d_in, const int* in_sizes, int n_in,
                              void* d_out, int out_size) {
    const int*   dec  = (const int*)d_in[0];
    const float* EO   = (const float*)d_in[1];
    const int*   idxs = (const int*)d_in[2];
    const float* prev = (const float*)d_in[3];
    const float* sr   = (const float*)d_in[4];
    int off = (n_in >= 17 && in_sizes[5] == 1) ? 1 : 0;
    const float* emb  = (const float*)d_in[5 + off];
    const float* W_ih = (const float*)d_in[6 + off];
    const float* W_hh = (const float*)d_in[7 + off];
    const float* b_ih = (const float*)d_in[8 + off];
    const float* b_hh = (const float*)d_in[9 + off];
    const float* Wg_w = (const float*)d_in[12 + off];
    const float* Wg_b = (const float*)d_in[13 + off];
    const float* Wc_w = (const float*)d_in[14 + off];
    const float* Wc_b = (const float*)d_in[15 + off];

    float* out    = (float*)d_out;
    float* out_dh = out + (size_t)BB * VO;
    float* out_sr = out_dh + (size_t)BB * HH;

    cudaFuncSetAttribute(k_big,   cudaFuncAttributeMaxDynamicSharedMemorySize, DYN_BIG);
    cudaFuncSetAttribute(k_gates, cudaFuncAttributeMaxDynamicSharedMemorySize, DYN_GATES);

    k_gates<<<12, 256, DYN_GATES>>>(dec, sr, emb, prev, W_ih, b_ih, W_hh, b_hh);
    k_gru<<<BB, HH>>>(prev, out_dh);
    k_big<<<NBG + NBE, 256, DYN_BIG>>>(Wg_w, Wg_b, EO, Wc_w, Wc_b, idxs);
    k_merge<<<BB, 256>>>();
    k_out<<<dim3((VV + 2047) / 2048, BB), 512>>>(out);
    k_tail<<<BB, 256>>>(idxs, dec, EO, out, out_sr);
}